// round 1
// baseline (speedup 1.0000x reference)
#include <cuda_runtime.h>

#define Bb   8
#define Nn   2048
#define Cc   64
#define MIDm 256
#define KK   16
#define R2c  0.0225f
#define EPSc 1e-5f

// ---------------- scratch (device globals, no allocation) ----------------
__device__ __align__(16) int    g_idx[Bb*Nn*KK];      // [b][n][16]
__device__ __align__(16) float  g_feat[Bb*Nn*Cc];     // [b][n][c]  = w1[:,3:]@f
__device__ __align__(16) float  g_m[Bb*Cc*Nn];        // [b][c][n]  = max_k x
__device__ __align__(16) float  g_y[Bb*MIDm*Nn];      // [b][c][n]
__device__ __align__(16) float  g_z[Bb*Cc*Nn];        // [b][c][n]
__device__ __align__(16) float  g_w2t[Cc*MIDm];       // [k][o] = w2[o][k]
__device__ __align__(16) float  g_w3t[MIDm*Cc];       // [k][c] = w3[c][k]
__device__ double g_s1[Cc],   g_ss1[Cc];
__device__ double g_s2[MIDm], g_ss2[MIDm];
__device__ double g_s3[Cc],   g_ss3[Cc];

// ---------------- K_prep: weight transposes + zero stats ----------------
__global__ void k_prep(const float* __restrict__ w2, const float* __restrict__ w3) {
    int i = blockIdx.x * 256 + threadIdx.x;
    if (i < Cc*MIDm) {
        int o = i >> 6, k = i & 63;           // w2: (256,64) row-major
        g_w2t[k*MIDm + o] = w2[i];
        int c = i >> 8, kk = i & 255;         // w3: (64,256) row-major
        g_w3t[kk*Cc + c] = w3[i];
    }
    if (i < Cc)   { g_s1[i]=0.0; g_ss1[i]=0.0; g_s3[i]=0.0; g_ss3[i]=0.0; }
    if (i < MIDm) { g_s2[i]=0.0; g_ss2[i]=0.0; }
}

// ---------------- K_gfeat: g[b][n][c] = sum_cp w1[c][3+cp] * f[b][cp][n] ----------------
__global__ void __launch_bounds__(256) k_gfeat(const float* __restrict__ f,
                                               const float* __restrict__ w1) {
    __shared__ __align__(16) float w1t[64*68];   // [cp][c], padded
    __shared__ __align__(16) float fs[64*32];    // [cp][nl]
    __shared__ __align__(16) float gs[32*68];    // [nl][c], padded
    int tid = threadIdx.x;
    int b  = blockIdx.x >> 6;
    int n0 = (blockIdx.x & 63) << 5;

    for (int i = tid; i < 64*64; i += 256) {
        int c = i >> 6, cp = i & 63;
        w1t[cp*68 + c] = w1[c*67 + 3 + cp];
    }
    for (int i = tid; i < 64*32; i += 256) {
        int cp = i >> 5, nl = i & 31;
        fs[i] = f[(b*64 + cp)*2048 + n0 + nl];
    }
    __syncthreads();

    int nl = tid & 31, cg = tid >> 5;    // channels cg*8 .. cg*8+7
    float acc[8];
    #pragma unroll
    for (int i = 0; i < 8; i++) acc[i] = 0.f;

    #pragma unroll 8
    for (int cp = 0; cp < 64; cp++) {
        float fv = fs[cp*32 + nl];
        float4 wa = *(const float4*)&w1t[cp*68 + cg*8];
        float4 wb = *(const float4*)&w1t[cp*68 + cg*8 + 4];
        acc[0] = fmaf(wa.x, fv, acc[0]);
        acc[1] = fmaf(wa.y, fv, acc[1]);
        acc[2] = fmaf(wa.z, fv, acc[2]);
        acc[3] = fmaf(wa.w, fv, acc[3]);
        acc[4] = fmaf(wb.x, fv, acc[4]);
        acc[5] = fmaf(wb.y, fv, acc[5]);
        acc[6] = fmaf(wb.z, fv, acc[6]);
        acc[7] = fmaf(wb.w, fv, acc[7]);
    }
    #pragma unroll
    for (int i = 0; i < 8; i++) gs[nl*68 + cg*8 + i] = acc[i];
    __syncthreads();
    for (int i = tid; i < 2048; i += 256) {
        int nn = i >> 6, c = i & 63;
        g_feat[(b*2048 + n0 + nn)*64 + c] = gs[nn*68 + c];
    }
}

// ---------------- K_ballq: warp-per-point ascending scan, early exit ----------------
__global__ void __launch_bounds__(512) k_ballq(const float* __restrict__ p) {
    __shared__ float px[2048], py[2048], pz[2048];
    __shared__ int   ob[16][16];
    int tid = threadIdx.x;
    int b  = blockIdx.x >> 7;             // 128 blocks per batch
    int n0 = (blockIdx.x & 127) << 4;     // 16 points per block

    for (int i = tid; i < 2048; i += 512) {
        const float* pp = p + (size_t)(b*2048 + i)*3;
        px[i] = pp[0]; py[i] = pp[1]; pz[i] = pp[2];
    }
    __syncthreads();

    int w = tid >> 5, lane = tid & 31;
    int n = n0 + w;
    float qx = px[n], qy = py[n], qz = pz[n];
    int cnt = 0;
    for (int j0 = 0; j0 < 2048; j0 += 32) {
        int j = j0 + lane;
        float dx = __fsub_rn(px[j], qx);
        float dy = __fsub_rn(py[j], qy);
        float dz = __fsub_rn(pz[j], qz);
        float d2 = __fadd_rn(__fadd_rn(__fmul_rn(dx,dx), __fmul_rn(dy,dy)), __fmul_rn(dz,dz));
        bool q = d2 < R2c;
        unsigned mask = __ballot_sync(0xffffffffu, q);
        if (mask) {
            int r = cnt + __popc(mask & ((1u << lane) - 1u));
            if (q && r < 16) ob[w][r] = j;
            cnt += __popc(mask);
            if (cnt >= 16) break;
        }
    }
    __syncwarp();
    if (cnt < 16) {                       // pad with first neighbor (self always qualifies)
        int first = ob[w][0];
        if (lane >= cnt && lane < 16) ob[w][lane] = first;
        __syncwarp();
    }
    if (lane < 16) g_idx[(b*2048 + n)*16 + lane] = ob[w][lane];
}

// ---------------- K_agg: x = g[j] + w1p@dp ; stats1 + max over K ----------------
__global__ void __launch_bounds__(256) k_agg(const float* __restrict__ p,
                                             const float* __restrict__ w1) {
    __shared__ float ms[64*8];
    __shared__ float s1s[64], q1s[64];
    int tid = threadIdx.x;
    if (tid < 64) { s1s[tid] = 0.f; q1s[tid] = 0.f; }
    __syncthreads();

    int b  = blockIdx.x >> 8;
    int n0 = (blockIdx.x & 255) << 3;   // 8 points per block (1 per warp)
    int w = tid >> 5, lane = tid & 31;
    int n = n0 + w;
    int c0 = lane, c1 = lane + 32;

    float wx0 = w1[c0*67+0], wy0 = w1[c0*67+1], wz0 = w1[c0*67+2];
    float wx1 = w1[c1*67+0], wy1 = w1[c1*67+1], wz1 = w1[c1*67+2];
    const float* pc = p + (size_t)(b*2048 + n)*3;
    float cx = pc[0], cy = pc[1], cz = pc[2];
    int jreg = g_idx[(b*2048 + n)*16 + (lane & 15)];

    float mx0 = -3.402823466e38f, mx1 = -3.402823466e38f;
    float s0 = 0.f, q0 = 0.f, s1v = 0.f, q1v = 0.f;
    #pragma unroll
    for (int k = 0; k < 16; k++) {
        int j = __shfl_sync(0xffffffffu, jreg, k);
        const float* gp = g_feat + (size_t)(b*2048 + j)*64;
        float ga = __ldg(gp + c0);
        float gb = __ldg(gp + c1);
        const float* pj = p + (size_t)(b*2048 + j)*3;
        float dx = pj[0] - cx, dy = pj[1] - cy, dz = pj[2] - cz;
        float v0 = fmaf(wx0, dx, fmaf(wy0, dy, fmaf(wz0, dz, ga)));
        float v1 = fmaf(wx1, dx, fmaf(wy1, dy, fmaf(wz1, dz, gb)));
        mx0 = fmaxf(mx0, v0); mx1 = fmaxf(mx1, v1);
        s0 += v0; q0 = fmaf(v0, v0, q0);
        s1v += v1; q1v = fmaf(v1, v1, q1v);
    }
    ms[c0*8 + w] = mx0;
    ms[c1*8 + w] = mx1;
    atomicAdd(&s1s[c0], s0);  atomicAdd(&q1s[c0], q0);
    atomicAdd(&s1s[c1], s1v); atomicAdd(&q1s[c1], q1v);
    __syncthreads();
    for (int i = tid; i < 512; i += 256) {
        int c = i >> 3, nl = i & 7;
        g_m[(b*64 + c)*2048 + n0 + nl] = ms[i];
    }
    if (tid < 64) {
        atomicAdd(&g_s1[tid],  (double)s1s[tid]);
        atomicAdd(&g_ss1[tid], (double)q1s[tid]);
    }
}

// ---------------- K_mlp1: y = w2 @ relu(bn1(m)) ; stats2 ----------------
__global__ void __launch_bounds__(256, 2) k_mlp1(const float* __restrict__ g1,
                                                 const float* __restrict__ b1) {
    __shared__ __align__(16) float hs[64*64];
    __shared__ float sc[64], sh[64];
    __shared__ float s2s[MIDm], q2s[MIDm];
    int tid = threadIdx.x;
    if (tid < 64) {
        double cnt = (double)(Bb*Nn*KK);
        double mu  = g_s1[tid] / cnt;
        double var = g_ss1[tid] / cnt - mu*mu;
        float s = g1[tid] * rsqrtf((float)var + EPSc);
        sc[tid] = s;
        sh[tid] = b1[tid] - (float)mu * s;
    }
    if (tid < 256) { s2s[tid] = 0.f; q2s[tid] = 0.f; }
    __syncthreads();

    int b  = blockIdx.x >> 5;
    int n0 = (blockIdx.x & 31) << 6;
    for (int i = tid; i < 4096; i += 256) {
        int c = i >> 6, nl = i & 63;
        float v = g_m[(b*64 + c)*2048 + n0 + nl];
        hs[i] = fmaxf(0.f, fmaf(v, sc[c], sh[c]));
    }
    __syncthreads();

    int nc = tid & 7, cc = tid >> 3;    // n: nc*8..+7 ; c: cc*8..+7
    float acc[8][8];
    #pragma unroll
    for (int i = 0; i < 8; i++)
        #pragma unroll
        for (int j = 0; j < 8; j++) acc[i][j] = 0.f;

    #pragma unroll 4
    for (int k = 0; k < 64; k++) {
        float4 h0 = *(const float4*)&hs[k*64 + nc*8];
        float4 h1 = *(const float4*)&hs[k*64 + nc*8 + 4];
        float4 wA = __ldg((const float4*)&g_w2t[k*256 + cc*8]);
        float4 wB = __ldg((const float4*)&g_w2t[k*256 + cc*8 + 4]);
        float hv[8] = {h0.x,h0.y,h0.z,h0.w,h1.x,h1.y,h1.z,h1.w};
        float wv[8] = {wA.x,wA.y,wA.z,wA.w,wB.x,wB.y,wB.z,wB.w};
        #pragma unroll
        for (int ci = 0; ci < 8; ci++)
            #pragma unroll
            for (int nj = 0; nj < 8; nj++)
                acc[ci][nj] = fmaf(wv[ci], hv[nj], acc[ci][nj]);
    }
    #pragma unroll
    for (int ci = 0; ci < 8; ci++) {
        int c = cc*8 + ci;
        float s = 0.f, q = 0.f;
        #pragma unroll
        for (int nj = 0; nj < 8; nj++) { float v = acc[ci][nj]; s += v; q = fmaf(v, v, q); }
        atomicAdd(&s2s[c], s); atomicAdd(&q2s[c], q);
        float* yp = &g_y[(size_t)(b*256 + c)*2048 + n0 + nc*8];
        *(float4*)yp       = make_float4(acc[ci][0], acc[ci][1], acc[ci][2], acc[ci][3]);
        *(float4*)(yp + 4) = make_float4(acc[ci][4], acc[ci][5], acc[ci][6], acc[ci][7]);
    }
    __syncthreads();
    if (tid < 256) {
        atomicAdd(&g_s2[tid],  (double)s2s[tid]);
        atomicAdd(&g_ss2[tid], (double)q2s[tid]);
    }
}

// ---------------- K_mlp2: z = w3 @ relu(bn2(y)) ; stats3 ----------------
__global__ void __launch_bounds__(256, 2) k_mlp2(const float* __restrict__ g2,
                                                 const float* __restrict__ b2) {
    __shared__ __align__(16) float hs[64*128];   // 32 KB
    __shared__ float sc[256], sh[256];
    __shared__ float s3s[64], q3s[64];
    int tid = threadIdx.x;
    if (tid < 256) {
        double cnt = (double)(Bb*Nn);
        double mu  = g_s2[tid] / cnt;
        double var = g_ss2[tid] / cnt - mu*mu;
        float s = g2[tid] * rsqrtf((float)var + EPSc);
        sc[tid] = s;
        sh[tid] = b2[tid] - (float)mu * s;
    }
    if (tid < 64) { s3s[tid] = 0.f; q3s[tid] = 0.f; }
    __syncthreads();

    int b  = blockIdx.x >> 4;
    int n0 = (blockIdx.x & 15) << 7;    // 128 n per block
    int nc = tid & 15, cc = tid >> 4;   // n: nc*8..+7 ; c: cc*4..+3
    float acc[4][8];
    #pragma unroll
    for (int i = 0; i < 4; i++)
        #pragma unroll
        for (int j = 0; j < 8; j++) acc[i][j] = 0.f;

    for (int k0 = 0; k0 < 256; k0 += 64) {
        for (int i = tid; i < 8192; i += 256) {
            int kk = i >> 7, nl = i & 127;
            int c = k0 + kk;
            float v = g_y[(size_t)(b*256 + c)*2048 + n0 + nl];
            hs[i] = fmaxf(0.f, fmaf(v, sc[c], sh[c]));
        }
        __syncthreads();
        #pragma unroll 4
        for (int kk = 0; kk < 64; kk++) {
            float4 w  = __ldg((const float4*)&g_w3t[(k0+kk)*64 + cc*4]);
            float4 ha = *(const float4*)&hs[kk*128 + nc*8];
            float4 hb = *(const float4*)&hs[kk*128 + nc*8 + 4];
            float hv[8] = {ha.x,ha.y,ha.z,ha.w,hb.x,hb.y,hb.z,hb.w};
            float wv[4] = {w.x,w.y,w.z,w.w};
            #pragma unroll
            for (int ci = 0; ci < 4; ci++)
                #pragma unroll
                for (int nj = 0; nj < 8; nj++)
                    acc[ci][nj] = fmaf(wv[ci], hv[nj], acc[ci][nj]);
        }
        __syncthreads();
    }
    #pragma unroll
    for (int ci = 0; ci < 4; ci++) {
        int c = cc*4 + ci;
        float s = 0.f, q = 0.f;
        #pragma unroll
        for (int nj = 0; nj < 8; nj++) { float v = acc[ci][nj]; s += v; q = fmaf(v, v, q); }
        atomicAdd(&s3s[c], s); atomicAdd(&q3s[c], q);
        float* zp = &g_z[(size_t)(b*64 + c)*2048 + n0 + nc*8];
        *(float4*)zp       = make_float4(acc[ci][0], acc[ci][1], acc[ci][2], acc[ci][3]);
        *(float4*)(zp + 4) = make_float4(acc[ci][4], acc[ci][5], acc[ci][6], acc[ci][7]);
    }
    __syncthreads();
    if (tid < 64) {
        atomicAdd(&g_s3[tid],  (double)s3s[tid]);
        atomicAdd(&g_ss3[tid], (double)q3s[tid]);
    }
}

// ---------------- K_out: relu(bn3(z) + f) ----------------
__global__ void __launch_bounds__(256) k_out(const float* __restrict__ f,
                                             const float* __restrict__ g3,
                                             const float* __restrict__ b3,
                                             float* __restrict__ out) {
    __shared__ float sc[64], sh[64];
    int tid = threadIdx.x;
    if (tid < 64) {
        double cnt = (double)(Bb*Nn);
        double mu  = g_s3[tid] / cnt;
        double var = g_ss3[tid] / cnt - mu*mu;
        float s = g3[tid] * rsqrtf((float)var + EPSc);
        sc[tid] = s;
        sh[tid] = b3[tid] - (float)mu * s;
    }
    __syncthreads();
    int i = blockIdx.x * 256 + tid;     // float4 index
    int base = i * 4;
    int c = (base >> 11) & 63;
    float4 z  = *(const float4*)&g_z[base];
    float4 fv = *(const float4*)&f[base];
    float4 o;
    o.x = fmaxf(0.f, fmaf(z.x, sc[c], sh[c]) + fv.x);
    o.y = fmaxf(0.f, fmaf(z.y, sc[c], sh[c]) + fv.y);
    o.z = fmaxf(0.f, fmaf(z.z, sc[c], sh[c]) + fv.z);
    o.w = fmaxf(0.f, fmaf(z.w, sc[c], sh[c]) + fv.w);
    *(float4*)&out[base] = o;
}

// ---------------- launch ----------------
extern "C" void kernel_launch(void* const* d_in, const int* in_sizes, int n_in,
                              void* d_out, int out_size) {
    const float* p  = (const float*)d_in[0];
    const float* f  = (const float*)d_in[1];
    const float* w1 = (const float*)d_in[2];
    const float* g1 = (const float*)d_in[3];
    const float* b1 = (const float*)d_in[4];
    const float* w2 = (const float*)d_in[5];
    const float* g2 = (const float*)d_in[6];
    const float* b2 = (const float*)d_in[7];
    const float* w3 = (const float*)d_in[8];
    const float* g3 = (const float*)d_in[9];
    const float* b3 = (const float*)d_in[10];
    float* out = (float*)d_out;

    k_prep <<<64,   256>>>(w2, w3);
    k_gfeat<<<512,  256>>>(f, w1);
    k_ballq<<<1024, 512>>>(p);
    k_agg  <<<2048, 256>>>(p, w1);
    k_mlp1 <<<256,  256>>>(g1, b1);
    k_mlp2 <<<128,  256>>>(g2, b2);
    k_out  <<<1024, 256>>>(f, g3, b3, out);
}